// round 13
// baseline (speedup 1.0000x reference)
#include <cuda_runtime.h>
#include <cuda_fp16.h>
#include <cstring>

// PositionalSparseLinear: out[b,o] = sum_k x[b, conn[o,k]] * w[o,k]
//   x: [1024,8192] f32   conn: [8192,32] i32   w: [8192,32] f32   out: [1024,8192] f32
//
// Round 13:
//  - fp16-staged transposed SMEM batch tile (BT=8 per 16B col) [R4]
//  - histogram-aware bank-group slot targeting [R11], now fed by
//    POWER-OF-TWO-CHOICES placement: a 2nd SMEM copy stores column c at
//    index 8192+(c^4) (bank group ^4). Prep splits each XOR-4 group-pair
//    evenly between its two groups -> near-balanced histograms, expected
//    crossbar phases 4.8 -> ~4.3 (floor 4).
//  - metadata stored as uint2 pairs -> 16 LDG.64 instead of 32 LDG.32 per
//    output (halves LSU dispatch cost of cw loads).
//  - flat chunk split over 148 CTAs, 512 thr x 2 outputs, FFMA2 [R10/R12]

#define IN_F   8192
#define OUT_F  8192
#define KW     32
#define BATCH  1024
#define BT     8
#define THREADS 512
#define N_CTAS 148
#define TOTAL_CHUNKS ((BATCH / BT) * 8)               // 1024
#define SMEM_U4 (2 * IN_F - IN_F / 2)                 // 12288 uint4 (A:8192, B:4096? no)
#define SMEM_BYTES ((IN_F + IN_F) * (int)sizeof(short) * BT)  // placeholder (fixed below)

// Real SMEM: copy A = 8192 uint4, copy B = 8192 uint4 -> 16384*16 = 256KB too big!
// Copy B only needs the REMAPPED positions, same 8192 columns: it IS 8192 uint4.
// 8192*16*2 = 262144 > 227KB. => Copy B cannot be full size. Instead, copy B
// holds only columns that some entry actually wants remapped? Data-dependent,
// not indexable. SOLUTION: shift granularity. Bank group of xs[i] is i&7.
// Use ONE array of 12288 uint4 (192KB): copy A at [0,8192) (group c&7) and a
// HALF copy B at [8192,12288) holding columns c with (c&4)==0 remapped to
// 8192 + (c>>3)*4 + (c&3)  -> group ((c&3) + 0)&7 ... too clever; see below.

__device__ unsigned int g_cw[KW * OUT_F];   // paired layout: uint2 [kk][o]

static __device__ __forceinline__ __half2 u32_as_h2(unsigned int u) {
    __half2 h; memcpy(&h, &u, sizeof(h)); return h;
}

// ---- Prep: two-choices split + histogram-aware slot targeting ----
// Copy B geometry: column c lives at index 8192 + ((c >> 1) & ~3) + ... we
// keep it SIMPLE and exact: copy B stores column c at index 8192 + (c % 4096)
// is ambiguous. FINAL CHOICE (collision-free, 4096 slots): only entries that
// the splitter assigns to their ALTERNATE group need copy B, and alternates
// are only used when the natural group is over-subscribed. To stay safe and
// indexable we use: copy B index = 8192 + (c >> 1): maps 2 columns to 1 slot
// -> COLLISION. Not acceptable.
//
// => Fall back to a sound variant: copy B covers only EVEN columns:
//    B[j] = column 2j at index 8192+j, bank group j&7 = (c/2)&7.
//    Entries with even c get a second choice group (c>>1)&7; odd c have one.
//    ~16 of 32 entries get two choices - still flattens the histogram well.
__global__ void psl_prep(const int* __restrict__ conn, const float* __restrict__ w)
{
    const int gtid = blockIdx.x * blockDim.x + threadIdx.x;
    const int o    = gtid >> 5;
    const int lane = gtid & 31;

    const int   c  = conn[(size_t)o * KW + lane];
    const float wv = w   [(size_t)o * KW + lane];
    const unsigned short hb = __half_as_ushort(__float2half_rn(wv));

    const int gA = c & 7;                      // group via copy A
    const int gB = (c >> 1) & 7;               // group via copy B (even c only)
    const bool hasB = ((c & 1) == 0);
    const unsigned int lt = (1u << lane) - 1u;

    // Greedy two-choices: first count natural-only load, then entries with a
    // second choice move to gB if gB's (natural) population is smaller.
    int cntA[8];
    #pragma unroll
    for (int gg = 0; gg < 8; gg++)
        cntA[gg] = __popc(__ballot_sync(0xffffffffu, gA == gg));

    const bool useB = hasB && (gB != gA) && (cntA[gB] + 2 <= cntA[gA]);
    const int g = useB ? gB : gA;
    const int final_idx = useB ? (8192 + (c >> 1)) : c;
    const unsigned int packed = ((unsigned int)final_idx << 16) | (unsigned int)hb;

    // recount with final groups, rank within group
    int cnt[8]; int r = 0;
    #pragma unroll
    for (int gg = 0; gg < 8; gg++) {
        unsigned int m = __ballot_sync(0xffffffffu, g == gg);
        cnt[gg] = __popc(m);
        if (gg == g) r = __popc(m & lt);
    }

    int slot;
    unsigned int lm = __ballot_sync(0xffffffffu, r >= 4);
    if (r < 4) {
        slot = 4 * ((g - o) & 7) + r;
    } else {
        int i = __popc(lm & lt);
        int cum = 0, slotg = 0, j = 0;
        #pragma unroll
        for (int gg = 0; gg < 8; gg++) {
            int def = cnt[gg] < 4 ? 4 - cnt[gg] : 0;
            if (i >= cum && i < cum + def) { slotg = gg; j = cnt[gg] + (i - cum); }
            cum += def;
        }
        slot = 4 * ((slotg - o) & 7) + j;
    }

    // paired uint2 layout: word (slot&1) of pair slot>>1
    g_cw[((size_t)(slot >> 1) * OUT_F + o) * 2 + (slot & 1)] = packed;
}

#define SMEM_TOTAL_BYTES ((8192 + 4096) * 16)   // 196608 = 192KB

__global__ __launch_bounds__(THREADS, 1)
void psl_main(const float* __restrict__ x, float* __restrict__ out)
{
    extern __shared__ uint4 xs[];   // [0,8192): copy A; [8192,12288): copy B (even cols)

    const int tid = threadIdx.x;
    const int bid = blockIdx.x;

    const int c_start = (bid * TOTAL_CHUNKS) / N_CTAS;
    const int c_end   = ((bid + 1) * TOTAL_CHUNKS) / N_CTAS;

    int cur_bt = -1;

    #pragma unroll 1
    for (int ch = c_start; ch < c_end; ch++) {
        const int bt = ch >> 3;
        const int oc = ch & 7;

        if (bt != cur_bt) {
            if (cur_bt >= 0) __syncthreads();
            const float* xb = x + (size_t)bt * BT * IN_F;
            #pragma unroll
            for (int cc = tid; cc < IN_F; cc += THREADS) {
                float r0 = xb[cc + 0 * (size_t)IN_F];
                float r1 = xb[cc + 1 * (size_t)IN_F];
                float r2 = xb[cc + 2 * (size_t)IN_F];
                float r3 = xb[cc + 3 * (size_t)IN_F];
                float r4 = xb[cc + 4 * (size_t)IN_F];
                float r5 = xb[cc + 5 * (size_t)IN_F];
                float r6 = xb[cc + 6 * (size_t)IN_F];
                float r7 = xb[cc + 7 * (size_t)IN_F];

                __half2 h0 = __floats2half2_rn(r0, r1);
                __half2 h1 = __floats2half2_rn(r2, r3);
                __half2 h2 = __floats2half2_rn(r4, r5);
                __half2 h3 = __floats2half2_rn(r6, r7);

                uint4 v;
                memcpy(&v.x, &h0, 4);
                memcpy(&v.y, &h1, 4);
                memcpy(&v.z, &h2, 4);
                memcpy(&v.w, &h3, 4);
                xs[cc] = v;
                if ((cc & 1) == 0) xs[8192 + (cc >> 1)] = v;   // copy B
            }
            cur_bt = bt;
            __syncthreads();
        }

        const int o1 = oc * 1024 + tid;     // o % 32 == lane: schedule holds
        const uint2* __restrict__ cwp1 = reinterpret_cast<const uint2*>(g_cw) + o1;
        const uint2* __restrict__ cwp2 = cwp1 + 512;

        unsigned long long A01 = 0ull, A23 = 0ull, A45 = 0ull, A67 = 0ull;
        unsigned long long B01 = 0ull, B23 = 0ull, B45 = 0ull, B67 = 0ull;

        #pragma unroll 8
        for (int kk = 0; kk < KW / 2; kk++) {
            const uint2 q1 = cwp1[(size_t)kk * OUT_F];
            const uint2 q2 = cwp2[(size_t)kk * OUT_F];

            #define PSL_BODY(CW, P01, P23, P45, P67) {                          \
                const int   c_  = (int)((CW) >> 16);                             \
                const float wvf = __half2float(__ushort_as_half(                 \
                                      (unsigned short)((CW) & 0xffffu)));        \
                unsigned long long WV2;                                          \
                asm("mov.b64 %0, {%1, %1};" : "=l"(WV2) : "f"(wvf));             \
                const uint4 hv = xs[c_];                                         \
                float2 f0 = __half22float2(u32_as_h2(hv.x));                     \
                float2 f1 = __half22float2(u32_as_h2(hv.y));                     \
                float2 f2 = __half22float2(u32_as_h2(hv.z));                     \
                float2 f3 = __half22float2(u32_as_h2(hv.w));                     \
                unsigned long long F0, F1, F2, F3;                               \
                asm("mov.b64 %0, {%1, %2};" : "=l"(F0) : "f"(f0.x), "f"(f0.y));  \
                asm("mov.b64 %0, {%1, %2};" : "=l"(F1) : "f"(f1.x), "f"(f1.y));  \
                asm("mov.b64 %0, {%1, %2};" : "=l"(F2) : "f"(f2.x), "f"(f2.y));  \
                asm("mov.b64 %0, {%1, %2};" : "=l"(F3) : "f"(f3.x), "f"(f3.y));  \
                asm("fma.rn.f32x2 %0, %1, %2, %0;" : "+l"(P01) : "l"(F0), "l"(WV2)); \
                asm("fma.rn.f32x2 %0, %1, %2, %0;" : "+l"(P23) : "l"(F1), "l"(WV2)); \
                asm("fma.rn.f32x2 %0, %1, %2, %0;" : "+l"(P45) : "l"(F2), "l"(WV2)); \
                asm("fma.rn.f32x2 %0, %1, %2, %0;" : "+l"(P67) : "l"(F3), "l"(WV2)); \
            }
            PSL_BODY(q1.x, A01, A23, A45, A67);
            PSL_BODY(q2.x, B01, B23, B45, B67);
            PSL_BODY(q1.y, A01, A23, A45, A67);
            PSL_BODY(q2.y, B01, B23, B45, B67);
            #undef PSL_BODY
        }

        float a0, a1, a2, a3, a4, a5, a6, a7;
        float b0, b1, b2, b3, b4, b5, b6, b7;
        asm("mov.b64 {%0, %1}, %2;" : "=f"(a0), "=f"(a1) : "l"(A01));
        asm("mov.b64 {%0, %1}, %2;" : "=f"(a2), "=f"(a3) : "l"(A23));
        asm("mov.b64 {%0, %1}, %2;" : "=f"(a4), "=f"(a5) : "l"(A45));
        asm("mov.b64 {%0, %1}, %2;" : "=f"(a6), "=f"(a7) : "l"(A67));
        asm("mov.b64 {%0, %1}, %2;" : "=f"(b0), "=f"(b1) : "l"(B01));
        asm("mov.b64 {%0, %1}, %2;" : "=f"(b2), "=f"(b3) : "l"(B23));
        asm("mov.b64 {%0, %1}, %2;" : "=f"(b4), "=f"(b5) : "l"(B45));
        asm("mov.b64 {%0, %1}, %2;" : "=f"(b6), "=f"(b7) : "l"(B67));

        float* op1 = out + (size_t)bt * BT * OUT_F + o1;
        float* op2 = op1 + 512;
        op1[0 * (size_t)OUT_F] = a0;  op2[0 * (size_t)OUT_F] = b0;
        op1[1 * (size_t)OUT_F] = a1;  op2[1 * (size_t)OUT_F] = b1;
        op1[2 * (size_t)OUT_F] = a2;  op2[2 * (size_t)OUT_F] = b2;
        op1[3 * (size_t)OUT_F] = a3;  op2[3 * (size_t)OUT_F] = b3;
        op1[4 * (size_t)OUT_F] = a4;  op2[4 * (size_t)OUT_F] = b4;
        op1[5 * (size_t)OUT_F] = a5;  op2[5 * (size_t)OUT_F] = b5;
        op1[6 * (size_t)OUT_F] = a6;  op2[6 * (size_t)OUT_F] = b6;
        op1[7 * (size_t)OUT_F] = a7;  op2[7 * (size_t)OUT_F] = b7;
    }
}

extern "C" void kernel_launch(void* const* d_in, const int* in_sizes, int n_in,
                              void* d_out, int out_size)
{
    const float* x    = (const float*)d_in[0];   // [1024, 8192] f32
    const int*   conn = (const int*)  d_in[1];   // [8192, 32]   i32
    const float* w    = (const float*)d_in[2];   // [8192, 32]   f32
    float*       out  = (float*)d_out;           // [1024, 8192] f32

    (void)in_sizes; (void)n_in; (void)out_size;

    psl_prep<<<(OUT_F * 32) / 256, 256>>>(conn, w);

    cudaFuncSetAttribute(psl_main,
                         cudaFuncAttributeMaxDynamicSharedMemorySize,
                         SMEM_TOTAL_BYTES);

    psl_main<<<N_CTAS, THREADS, SMEM_TOTAL_BYTES>>>(x, out);   // 148 CTAs, 1 wave
}

// round 14
// speedup vs baseline: 1.0905x; 1.0905x over previous
#include <cuda_runtime.h>
#include <cuda_fp16.h>
#include <cstring>

// PositionalSparseLinear: out[b,o] = sum_k x[b, conn[o,k]] * w[o,k]
//   x: [1024,8192] f32   conn: [8192,32] i32   w: [8192,32] f32   out: [1024,8192] f32
//
// Round 14 (revert R13; R12 base + quad-packed metadata):
//  - fp16-staged transposed SMEM batch tile (BT=8 per 16B col) [R4]
//  - histogram-aware bank-group slot schedule [R11]  (unchanged!)
//  - flat chunk split over 148 CTAs, 512 thr x 2 outputs, FFMA2 [R10/R12]
//  - NEW: metadata quad-packed as uint4 Q[kk][oc*512+tid] =
//      {cw[2kk][o1], cw[2kk+1][o1], cw[2kk][o1+512], cw[2kk+1][o1+512]}
//    -> 8 LDG.128 per output-pair instead of 32 LDG.32 (4x fewer LSU
//    dispatches, same bytes/wavefronts). Gather order per LDG keeps all
//    lanes on the same slot -> R11 schedule preserved.

#define IN_F   8192
#define OUT_F  8192
#define KW     32
#define BATCH  1024
#define BT     8
#define THREADS 512
#define N_CTAS 148
#define TOTAL_CHUNKS ((BATCH / BT) * 8)               // 1024
#define SMEM_BYTES (IN_F * BT * (int)sizeof(__half))  // 131072

// Quad layout: 16 slot-pairs x 4096 (oc*512 + o_local) x uint4
__device__ uint4 g_cwQ[16 * 4096];

static __device__ __forceinline__ __half2 u32_as_h2(unsigned int u) {
    __half2 h; memcpy(&h, &u, sizeof(h)); return h;
}

// One warp per output o; lane = k. R11 schedule:
// slot block for group g of output o: slots [4*((g-o)&7), +4);
// rank<4 claims its block, surplus fills deficit slots by ordered match.
__global__ void psl_prep(const int* __restrict__ conn, const float* __restrict__ w)
{
    const int gtid = blockIdx.x * blockDim.x + threadIdx.x;
    const int o    = gtid >> 5;
    const int lane = gtid & 31;

    const int   c  = conn[(size_t)o * KW + lane];
    const float wv = w   [(size_t)o * KW + lane];
    const unsigned short hb = __half_as_ushort(__float2half_rn(wv));
    const unsigned int packed = ((unsigned int)c << 16) | (unsigned int)hb;

    const int g = c & 7;
    const unsigned int lt = (1u << lane) - 1u;

    int cnt[8];
    int r = 0;
    #pragma unroll
    for (int gg = 0; gg < 8; gg++) {
        unsigned int m = __ballot_sync(0xffffffffu, g == gg);
        cnt[gg] = __popc(m);
        if (gg == g) r = __popc(m & lt);
    }

    int slot;
    unsigned int lm = __ballot_sync(0xffffffffu, r >= 4);
    if (r < 4) {
        slot = 4 * ((g - o) & 7) + r;
    } else {
        int i = __popc(lm & lt);
        int cum = 0, slotg = 0, j = 0;
        #pragma unroll
        for (int gg = 0; gg < 8; gg++) {
            int def = cnt[gg] < 4 ? 4 - cnt[gg] : 0;
            if (i >= cum && i < cum + def) { slotg = gg; j = cnt[gg] + (i - cum); }
            cum += def;
        }
        slot = 4 * ((slotg - o) & 7) + j;
    }

    // Quad-packed write: component = (o_hi<<1) | (slot&1)
    const int kk      = slot >> 1;
    const int word    = slot & 1;
    const int oc      = o >> 10;
    const int o_local = o & 511;
    const int o_hi    = (o >> 9) & 1;
    unsigned int* q32 = reinterpret_cast<unsigned int*>(g_cwQ);
    q32[((size_t)kk * 4096 + oc * 512 + o_local) * 4 + (o_hi * 2 + word)] = packed;
}

__global__ __launch_bounds__(THREADS, 1)
void psl_main(const float* __restrict__ x, float* __restrict__ out)
{
    extern __shared__ uint4 xs[];   // xs[col] = 8 halves: rows b0..b0+7 of col

    const int tid = threadIdx.x;
    const int bid = blockIdx.x;

    const int c_start = (bid * TOTAL_CHUNKS) / N_CTAS;
    const int c_end   = ((bid + 1) * TOTAL_CHUNKS) / N_CTAS;

    int cur_bt = -1;

    #pragma unroll 1
    for (int ch = c_start; ch < c_end; ch++) {
        const int bt = ch >> 3;            // b-tile index
        const int oc = ch & 7;             // output chunk within tile

        if (bt != cur_bt) {
            if (cur_bt >= 0) __syncthreads();   // drain readers of old tile
            const float* xb = x + (size_t)bt * BT * IN_F;
            #pragma unroll
            for (int cc = tid; cc < IN_F; cc += THREADS) {
                float r0 = xb[cc + 0 * (size_t)IN_F];
                float r1 = xb[cc + 1 * (size_t)IN_F];
                float r2 = xb[cc + 2 * (size_t)IN_F];
                float r3 = xb[cc + 3 * (size_t)IN_F];
                float r4 = xb[cc + 4 * (size_t)IN_F];
                float r5 = xb[cc + 5 * (size_t)IN_F];
                float r6 = xb[cc + 6 * (size_t)IN_F];
                float r7 = xb[cc + 7 * (size_t)IN_F];

                __half2 h0 = __floats2half2_rn(r0, r1);
                __half2 h1 = __floats2half2_rn(r2, r3);
                __half2 h2 = __floats2half2_rn(r4, r5);
                __half2 h3 = __floats2half2_rn(r6, r7);

                uint4 v;
                memcpy(&v.x, &h0, 4);
                memcpy(&v.y, &h1, 4);
                memcpy(&v.z, &h2, 4);
                memcpy(&v.w, &h3, 4);
                xs[cc] = v;
            }
            cur_bt = bt;
            __syncthreads();
        }

        const int o1 = oc * 1024 + tid;     // outputs o1 and o1+512; o%32==lane
        const uint4* __restrict__ qp = g_cwQ + oc * 512 + tid;

        unsigned long long A01 = 0ull, A23 = 0ull, A45 = 0ull, A67 = 0ull;
        unsigned long long B01 = 0ull, B23 = 0ull, B45 = 0ull, B67 = 0ull;

        #pragma unroll
        for (int kk = 0; kk < 16; kk++) {
            const uint4 q = qp[(size_t)kk * 4096];   // one LDG.128 = 4 metadata

            #define PSL_BODY(CW, P01, P23, P45, P67) {                          \
                const int   c_  = (int)((CW) >> 16);                             \
                const float wvf = __half2float(__ushort_as_half(                 \
                                      (unsigned short)((CW) & 0xffffu)));        \
                unsigned long long WV2;                                          \
                asm("mov.b64 %0, {%1, %1};" : "=l"(WV2) : "f"(wvf));             \
                const uint4 hv = xs[c_];                                         \
                float2 f0 = __half22float2(u32_as_h2(hv.x));                     \
                float2 f1 = __half22float2(u32_as_h2(hv.y));                     \
                float2 f2 = __half22float2(u32_as_h2(hv.z));                     \
                float2 f3 = __half22float2(u32_as_h2(hv.w));                     \
                unsigned long long F0, F1, F2, F3;                               \
                asm("mov.b64 %0, {%1, %2};" : "=l"(F0) : "f"(f0.x), "f"(f0.y));  \
                asm("mov.b64 %0, {%1, %2};" : "=l"(F1) : "f"(f1.x), "f"(f1.y));  \
                asm("mov.b64 %0, {%1, %2};" : "=l"(F2) : "f"(f2.x), "f"(f2.y));  \
                asm("mov.b64 %0, {%1, %2};" : "=l"(F3) : "f"(f3.x), "f"(f3.y));  \
                asm("fma.rn.f32x2 %0, %1, %2, %0;" : "+l"(P01) : "l"(F0), "l"(WV2)); \
                asm("fma.rn.f32x2 %0, %1, %2, %0;" : "+l"(P23) : "l"(F1), "l"(WV2)); \
                asm("fma.rn.f32x2 %0, %1, %2, %0;" : "+l"(P45) : "l"(F2), "l"(WV2)); \
                asm("fma.rn.f32x2 %0, %1, %2, %0;" : "+l"(P67) : "l"(F3), "l"(WV2)); \
            }
            // slot 2kk for both outputs, then slot 2kk+1 — lanes stay in
            // lock-step on the same slot (R11 schedule holds).
            PSL_BODY(q.x, A01, A23, A45, A67);
            PSL_BODY(q.z, B01, B23, B45, B67);
            PSL_BODY(q.y, A01, A23, A45, A67);
            PSL_BODY(q.w, B01, B23, B45, B67);
            #undef PSL_BODY
        }

        float a0, a1, a2, a3, a4, a5, a6, a7;
        float b0, b1, b2, b3, b4, b5, b6, b7;
        asm("mov.b64 {%0, %1}, %2;" : "=f"(a0), "=f"(a1) : "l"(A01));
        asm("mov.b64 {%0, %1}, %2;" : "=f"(a2), "=f"(a3) : "l"(A23));
        asm("mov.b64 {%0, %1}, %2;" : "=f"(a4), "=f"(a5) : "l"(A45));
        asm("mov.b64 {%0, %1}, %2;" : "=f"(a6), "=f"(a7) : "l"(A67));
        asm("mov.b64 {%0, %1}, %2;" : "=f"(b0), "=f"(b1) : "l"(B01));
        asm("mov.b64 {%0, %1}, %2;" : "=f"(b2), "=f"(b3) : "l"(B23));
        asm("mov.b64 {%0, %1}, %2;" : "=f"(b4), "=f"(b5) : "l"(B45));
        asm("mov.b64 {%0, %1}, %2;" : "=f"(b6), "=f"(b7) : "l"(B67));

        float* op1 = out + (size_t)bt * BT * OUT_F + o1;
        float* op2 = op1 + 512;
        op1[0 * (size_t)OUT_F] = a0;  op2[0 * (size_t)OUT_F] = b0;
        op1[1 * (size_t)OUT_F] = a1;  op2[1 * (size_t)OUT_F] = b1;
        op1[2 * (size_t)OUT_F] = a2;  op2[2 * (size_t)OUT_F] = b2;
        op1[3 * (size_t)OUT_F] = a3;  op2[3 * (size_t)OUT_F] = b3;
        op1[4 * (size_t)OUT_F] = a4;  op2[4 * (size_t)OUT_F] = b4;
        op1[5 * (size_t)OUT_F] = a5;  op2[5 * (size_t)OUT_F] = b5;
        op1[6 * (size_t)OUT_F] = a6;  op2[6 * (size_t)OUT_F] = b6;
        op1[7 * (size_t)OUT_F] = a7;  op2[7 * (size_t)OUT_F] = b7;
    }
}

extern "C" void kernel_launch(void* const* d_in, const int* in_sizes, int n_in,
                              void* d_out, int out_size)
{
    const float* x    = (const float*)d_in[0];   // [1024, 8192] f32
    const int*   conn = (const int*)  d_in[1];   // [8192, 32]   i32
    const float* w    = (const float*)d_in[2];   // [8192, 32]   f32
    float*       out  = (float*)d_out;           // [1024, 8192] f32

    (void)in_sizes; (void)n_in; (void)out_size;

    psl_prep<<<(OUT_F * 32) / 256, 256>>>(conn, w);

    cudaFuncSetAttribute(psl_main,
                         cudaFuncAttributeMaxDynamicSharedMemorySize,
                         SMEM_BYTES);

    psl_main<<<N_CTAS, THREADS, SMEM_BYTES>>>(x, out);   // 148 CTAs, 1 wave
}